// round 4
// baseline (speedup 1.0000x reference)
#include <cuda_runtime.h>

#define NJ 16384
#define JT 64
#define NB (NJ / JT)        // 256 blocks (kernel A)
#define NT_A 256
#define NT_B 256

#define A_PART (21 * 21 * 16384)
#define LD_OFF (2 * A_PART)
#define Z_OFF  (LD_OFF + 1)
#define Z_PART (21 * 16384)

__device__ float g_partial[NB];
__device__ unsigned int g_done;   // zero-init; reset by last block each launch

// per-j factor state (SoA, j fastest) — written by gp_state, read by gp_emit
__device__ __align__(16) float g_wr[21 * NJ], g_wi[21 * NJ];
__device__ __align__(16) float g_xr[20 * NJ], g_xi[20 * NJ];
__device__ __align__(16) float g_ur[20 * NJ], g_ui[20 * NJ];
__device__ __align__(16) float g_vr[20 * NJ], g_vi[20 * NJ];
__device__ __align__(16) float g_dr[21 * NJ], g_di[21 * NJ];

struct f4 { float v[4]; };
__device__ __forceinline__ f4 ld4(const float* p) {
    float4 t = *(const float4*)p;
    f4 r; r.v[0] = t.x; r.v[1] = t.y; r.v[2] = t.z; r.v[3] = t.w; return r;
}
__device__ __forceinline__ f4 ld4g(const float* p) {
    float4 t = __ldg((const float4*)p);
    f4 r; r.v[0] = t.x; r.v[1] = t.y; r.v[2] = t.z; r.v[3] = t.w; return r;
}
__device__ __forceinline__ void st4(float* p, const float* a) {
    *(float4*)p = make_float4(a[0], a[1], a[2], a[3]);
}

// ===================== Kernel A: factor state + zout + logdet =====================
__global__ __launch_bounds__(NT_A) void gp_state(
    const float* __restrict__ l00r, const float* __restrict__ l00i,
    const float* __restrict__ l01r, const float* __restrict__ l01i,
    const float* __restrict__ l02r, const float* __restrict__ l02i,
    const float* __restrict__ l11r, const float* __restrict__ l11i,
    const float* __restrict__ l12r, const float* __restrict__ l12i,
    const float* __restrict__ l22r, const float* __restrict__ l22i,
    const float* __restrict__ zre,  const float* __restrict__ zim,
    float* __restrict__ out)
{
    __shared__ __align__(16) float sm[182 * JT];
    __shared__ float sRed[10];
    __shared__ float sF[NB];
    __shared__ unsigned int sLast;

    float* sT1r  = sm;              // [16][JT]  row t*4+k
    float* sT1i  = sm + 16 * JT;
    float* sIS1r = sm + 32 * JT;    // [4][JT]
    float* sIS1i = sm + 36 * JT;
    float* sAr   = sm + 40 * JT;    // [16][JT]
    float* sAi   = sm + 56 * JT;
    float* sT2r  = sm + 72 * JT;    // [20][JT]
    float* sT2i  = sm + 92 * JT;
    float* sIS2r = sm + 112 * JT;   // [JT]
    float* sIS2i = sm + 113 * JT;
    float* sZr   = sm + 114 * JT;   // [21][JT]
    float* sZi   = sm + 135 * JT;
    float* sM2pr = sm + 156 * JT;   // [4][JT]
    float* sM2pi = sm + 160 * JT;
    float* sDXpr = sm + 164 * JT;   // [4][JT]
    float* sDXpi = sm + 168 * JT;
    float* sDYr  = sm + 172 * JT;   // [4][JT]
    float* sDYi  = sm + 176 * JT;
    float* sDXr  = sm + 180 * JT;   // [JT]
    float* sDXi  = sm + 181 * JT;

    const int flat = threadIdx.x;
    const int jj   = flat & 63;
    const int t    = flat >> 6;          // 0..3, all threads active in phase 1
    const int j    = blockIdx.x * JT + jj;

    // ---- z preload ----
    for (int idx = flat; idx < 21 * JT; idx += NT_A) {
        int q = idx >> 6, c = idx & 63;
        int gi = q * NJ + blockIdx.x * JT + c;
        sZr[idx] = zre[gi];
        sZi[idx] = zim[gi];
    }
    __syncthreads();

    // ---- Phase 1: per-(t, j) recursion ----
    {
        float ldacc = 0.f, M2r = 0.f, M2i = 0.f, dxr = 0.f, dxi = 0.f;
        const int m = t * NJ + j;
        float S1r = l11r[m], S1i = l11i[m];
        float T1re[4], T1im[4], Are[4], Aim[4];
#pragma unroll
        for (int k = 0; k < 4; ++k) {
            const int i0 = k * 65536 + m;
            float br = l00r[i0], bi = l00i[i0];
            float nrm = br * br + bi * bi;
            float rn = 1.0f / nrm;
            float ar = br * rn, ai = -bi * rn;     // 1/lam00
            float cr = l01r[i0], ci = l01i[i0];
            float bn = cr * cr + ci * ci;
            S1r -= bn * ar;  S1i -= bn * ai;
            T1re[k] = cr * ar - ci * ai;
            T1im[k] = cr * ai + ci * ar;
            Are[k] = ar; Aim[k] = ai;
            ldacc += __logf(nrm);
            sT1r[(t * 4 + k) * JT + jj] = T1re[k];
            sT1i[(t * 4 + k) * JT + jj] = T1im[k];
            sAr [(t * 4 + k) * JT + jj] = ar;
            sAi [(t * 4 + k) * JT + jj] = ai;
            // v_q for q = k*4 + t
            g_vr[(k * 4 + t) * NJ + j] = T1re[k];
            g_vi[(k * 4 + t) * NJ + j] = T1im[k];
        }
        // v for q = 16 + t is the constant -1
        g_vr[(16 + t) * NJ + j] = -1.f;
        g_vi[(16 + t) * NJ + j] = 0.f;

        float ns = S1r * S1r + S1i * S1i;
        float rs = 1.0f / ns;
        float is1r = S1r * rs, is1i = -S1i * rs;
        ldacc += __logf(ns);
        sIS1r[t * JT + jj] = is1r;
        sIS1i[t * JT + jj] = is1i;

        float Br[5], Bi[5];
#pragma unroll
        for (int a = 0; a < 4; ++a) {
            const int ib = (a * 4 + t) * NJ + j;
            Br[a] = l02r[ib]; Bi[a] = l02i[ib];
        }
        { const int ib = t * NJ + j; Br[4] = l12r[ib]; Bi[4] = l12i[ib]; }

        float Gr = -Br[4], Gi = -Bi[4];
#pragma unroll
        for (int a = 0; a < 4; ++a) {
            Gr += Br[a] * T1re[a] + Bi[a] * T1im[a];
            Gi += Bi[a] * T1re[a] - Br[a] * T1im[a];
        }
        // doty_t
        {
            float dyr = 0.f, dyi = 0.f;
#pragma unroll
            for (int i1 = 0; i1 < 4; ++i1) {
                float zr = sZr[(i1 * 4 + t) * JT + jj], zi = sZi[(i1 * 4 + t) * JT + jj];
                dyr += T1re[i1] * zr + T1im[i1] * zi;
                dyi += T1re[i1] * zi - T1im[i1] * zr;
            }
            float zr = sZr[(16 + t) * JT + jj], zi = sZi[(16 + t) * JT + jj];
            dyr -= zr; dyi -= zi;
            sDYr[t * JT + jj] = dyr;
            sDYi[t * JT + jj] = dyi;
        }
        // T2 rows (-> x state), M2 / dotx partials
#pragma unroll
        for (int i = 0; i < 5; ++i) {
            float t2r, t2i;
            if (i < 4) {
                float ur = T1re[i] * is1r - T1im[i] * is1i;
                float ui = T1re[i] * is1i + T1im[i] * is1r;
                t2r = ur * Gr - ui * Gi + Are[i] * Br[i] - Aim[i] * Bi[i];
                t2i = ur * Gi + ui * Gr + Are[i] * Bi[i] + Aim[i] * Br[i];
            } else {
                float ur = -is1r, ui = is1i;
                float d4 = 2.0f * is1i;
                t2r = ur * Gr - ui * Gi - d4 * Bi[4];
                t2i = ur * Gi + ui * Gr + d4 * Br[4];
            }
            const int row = (i < 4) ? (i * 4 + t) : (16 + t);
            sT2r[row * JT + jj] = t2r;
            sT2i[row * JT + jj] = t2i;
            g_xr[row * NJ + j] = t2r;
            g_xi[row * NJ + j] = t2i;
            M2r += Br[i] * t2r + Bi[i] * t2i;
            M2i += Br[i] * t2i - Bi[i] * t2r;
            float zr = sZr[row * JT + jj], zi = sZi[row * JT + jj];
            dxr += t2r * zr + t2i * zi;
            dxi += t2r * zi - t2i * zr;
        }
        sM2pr[t * JT + jj] = M2r;  sM2pi[t * JT + jj] = M2i;
        sDXpr[t * JT + jj] = dxr;  sDXpi[t * JT + jj] = dxi;

        ldacc *= 0.5f;
#pragma unroll
        for (int off = 16; off; off >>= 1)
            ldacc += __shfl_down_sync(0xffffffffu, ldacc, off);
        if ((flat & 31) == 0) sRed[flat >> 5] = ldacc;
    }
    __syncthreads();

    // ---- Phase 1.5: S2, 1/S2, dotx ----
    if (flat < JT) {
        float M2r = sM2pr[flat] + sM2pr[JT + flat] + sM2pr[2 * JT + flat] + sM2pr[3 * JT + flat];
        float M2i = sM2pi[flat] + sM2pi[JT + flat] + sM2pi[2 * JT + flat] + sM2pi[3 * JT + flat];
        float S2r = l22r[j] - M2r, S2i = l22i[j] - M2i;
        float ns2 = S2r * S2r + S2i * S2i;
        float rs2 = 1.0f / ns2;
        sIS2r[flat] = S2r * rs2;
        sIS2i[flat] = -S2i * rs2;
        float dxr = sDXpr[flat] + sDXpr[JT + flat] + sDXpr[2 * JT + flat] + sDXpr[3 * JT + flat]
                  - sZr[20 * JT + flat];
        float dxi = sDXpi[flat] + sDXpi[JT + flat] + sDXpi[2 * JT + flat] + sDXpi[3 * JT + flat]
                  - sZi[20 * JT + flat];
        sDXr[flat] = dxr;
        sDXi[flat] = dxi;
        float ext = 0.5f * __logf(ns2);
#pragma unroll
        for (int off = 16; off; off >>= 1)
            ext += __shfl_down_sync(0xffffffffu, ext, off);
        if ((flat & 31) == 0) sRed[8 + (flat >> 5)] = ext;
    }
    __syncthreads();

    if (flat == 0) {
        float s = 0.f;
#pragma unroll
        for (int i = 0; i < 10; ++i) s += sRed[i];
        g_partial[blockIdx.x] = s;
        __threadfence();
        unsigned int old = atomicAdd(&g_done, 1u);
        sLast = (old == NB - 1) ? 1u : 0u;
    }

    // ---- Phase 2: w/u/d state + zout, tasks (p, j-quad) ----
    for (int task = flat; task < 336; task += NT_A) {
        const int p   = task >> 4;
        const int jq  = task & 15;
        const int jj4 = jq * 4;
        const int j0  = blockIdx.x * JT + jj4;
        const int tt  = p & 3, i0 = p >> 2;

        f4 is2r = ld4(&sIS2r[jj4]), is2i = ld4(&sIS2i[jj4]);
        float wr[4], wi[4], ur[4], ui[4], dr[4], di[4];
        if (p < 20) {
            f4 t2r = ld4(&sT2r[p * JT + jj4]), t2i = ld4(&sT2i[p * JT + jj4]);
            f4 s1r = ld4(&sIS1r[tt * JT + jj4]), s1i = ld4(&sIS1i[tt * JT + jj4]);
#pragma unroll
            for (int e = 0; e < 4; ++e) {
                wr[e] = t2r.v[e] * is2r.v[e] - t2i.v[e] * is2i.v[e];
                wi[e] = t2r.v[e] * is2i.v[e] + t2i.v[e] * is2r.v[e];
            }
            if (i0 < 4) {
                f4 t1r = ld4(&sT1r[(tt * 4 + i0) * JT + jj4]);
                f4 t1i = ld4(&sT1i[(tt * 4 + i0) * JT + jj4]);
                f4 ar  = ld4(&sAr [(tt * 4 + i0) * JT + jj4]);
                f4 ai  = ld4(&sAi [(tt * 4 + i0) * JT + jj4]);
#pragma unroll
                for (int e = 0; e < 4; ++e) {
                    ur[e] = t1r.v[e] * s1r.v[e] - t1i.v[e] * s1i.v[e];
                    ui[e] = t1r.v[e] * s1i.v[e] + t1i.v[e] * s1r.v[e];
                    dr[e] = ar.v[e]; di[e] = ai.v[e];
                }
            } else {
#pragma unroll
                for (int e = 0; e < 4; ++e) {
                    ur[e] = -s1r.v[e]; ui[e] = s1i.v[e];
                    dr[e] = 0.f;       di[e] = 2.0f * s1i.v[e];
                }
            }
            st4(&g_ur[p * NJ + j0], ur);
            st4(&g_ui[p * NJ + j0], ui);
        } else {
#pragma unroll
            for (int e = 0; e < 4; ++e) {
                wr[e] = -is2r.v[e]; wi[e] = is2i.v[e];
                ur[e] = 0.f; ui[e] = 0.f;
                dr[e] = 0.f; di[e] = 2.0f * is2i.v[e];
            }
        }
        st4(&g_wr[p * NJ + j0], wr);
        st4(&g_wi[p * NJ + j0], wi);
        st4(&g_dr[p * NJ + j0], dr);
        st4(&g_di[p * NJ + j0], di);

        // zout_p = w*dotx + u*doty[tt] + d*z_p
        {
            f4 dxr = ld4(&sDXr[jj4]), dxi = ld4(&sDXi[jj4]);
            f4 dyr = ld4(&sDYr[tt * JT + jj4]), dyi = ld4(&sDYi[tt * JT + jj4]);
            f4 zpr = ld4(&sZr[p * JT + jj4]),  zpi = ld4(&sZi[p * JT + jj4]);
#pragma unroll
            for (int e = 0; e < 4; ++e) {
                float zar = wr[e] * dxr.v[e] - wi[e] * dxi.v[e]
                          + ur[e] * dyr.v[e] - ui[e] * dyi.v[e]
                          + dr[e] * zpr.v[e] - di[e] * zpi.v[e];
                float zai = wr[e] * dxi.v[e] + wi[e] * dxr.v[e]
                          + ur[e] * dyi.v[e] + ui[e] * dyr.v[e]
                          + dr[e] * zpi.v[e] + di[e] * zpr.v[e];
                out[Z_OFF + p * NJ + j0 + e]          = zar;
                out[Z_OFF + Z_PART + p * NJ + j0 + e] = zai;
            }
        }
    }

    // ---- fused logdet finalize ----
    __syncthreads();
    if (sLast) {
        if (flat < NB) sF[flat] = g_partial[flat];
        __syncthreads();
        for (int off = NB / 2; off; off >>= 1) {
            if (flat < off) sF[flat] += sF[flat + off];
            __syncthreads();
        }
        if (flat == 0) {
            out[LD_OFF] = sF[0];
            g_done = 0u;
        }
    }
}

// ===================== Kernel B: streaming A-matrix emitter =====================
// grid = 21 * 16 blocks; block p = blockIdx>>4 fixed -> uniform branches.
__global__ __launch_bounds__(NT_B) void gp_emit(float* __restrict__ out)
{
    const int p  = blockIdx.x >> 4;                       // 0..20
    const int jg = ((blockIdx.x & 15) << 8) + threadIdx.x; // 0..4095
    const int j4 = jg << 2;
    const int pj = p * NJ + j4;

    f4 wr = ld4g(&g_wr[pj]), wi = ld4g(&g_wi[pj]);
    f4 dr = ld4g(&g_dr[pj]), di = ld4g(&g_di[pj]);
    f4 ur, ui;
    if (p < 20) { ur = ld4g(&g_ur[pj]); ui = ld4g(&g_ui[pj]); }

    const int rowbase = p * 21 * NJ + j4;
#pragma unroll
    for (int q = 0; q < 21; ++q) {
        float cr[4], ci[4];
        if (q < 20) {
            f4 xr = ld4g(&g_xr[q * NJ + j4]), xi = ld4g(&g_xi[q * NJ + j4]);
#pragma unroll
            for (int e = 0; e < 4; ++e) {
                cr[e] = wr.v[e] * xr.v[e] + wi.v[e] * xi.v[e];
                ci[e] = wi.v[e] * xr.v[e] - wr.v[e] * xi.v[e];
            }
            if (p < 20 && (((p ^ q) & 3) == 0)) {
                f4 vr = ld4g(&g_vr[q * NJ + j4]), vi = ld4g(&g_vi[q * NJ + j4]);
#pragma unroll
                for (int e = 0; e < 4; ++e) {
                    cr[e] += ur.v[e] * vr.v[e] + ui.v[e] * vi.v[e];
                    ci[e] += ui.v[e] * vr.v[e] - ur.v[e] * vi.v[e];
                }
            }
        } else {
#pragma unroll
            for (int e = 0; e < 4; ++e) { cr[e] = -wr.v[e]; ci[e] = -wi.v[e]; }
        }
        if (p == q) {
#pragma unroll
            for (int e = 0; e < 4; ++e) { cr[e] += dr.v[e]; ci[e] += di.v[e]; }
        }
        st4(&out[rowbase + q * NJ], cr);
        st4(&out[A_PART + rowbase + q * NJ], ci);
    }
}

extern "C" void kernel_launch(void* const* d_in, const int* in_sizes, int n_in,
                              void* d_out, int out_size) {
    const float* l00r = (const float*)d_in[0];
    const float* l00i = (const float*)d_in[1];
    const float* l01r = (const float*)d_in[2];
    const float* l01i = (const float*)d_in[3];
    const float* l02r = (const float*)d_in[4];
    const float* l02i = (const float*)d_in[5];
    const float* l11r = (const float*)d_in[6];
    const float* l11i = (const float*)d_in[7];
    const float* l12r = (const float*)d_in[8];
    const float* l12i = (const float*)d_in[9];
    const float* l22r = (const float*)d_in[10];
    const float* l22i = (const float*)d_in[11];
    const float* zre  = (const float*)d_in[12];
    const float* zim  = (const float*)d_in[13];
    float* out = (float*)d_out;

    gp_state<<<NB, NT_A>>>(l00r, l00i, l01r, l01i, l02r, l02i,
                           l11r, l11i, l12r, l12i, l22r, l22i,
                           zre, zim, out);
    gp_emit<<<21 * 16, NT_B>>>(out);
}

// round 5
// speedup vs baseline: 1.5000x; 1.5000x over previous
#include <cuda_runtime.h>

#define NJ 16384
#define JT 64
#define NB (NJ / JT)        // 256 blocks
#define NT 1024

#define A_PART (21 * 21 * 16384)
#define LD_OFF (2 * A_PART)
#define Z_OFF  (LD_OFF + 1)
#define Z_PART (21 * 16384)

__device__ float g_partial[NB];
__device__ unsigned int g_done;   // zero-init; last block resets each launch

struct f4 { float v[4]; };
__device__ __forceinline__ f4 ld4(const float* p) {
    float4 t = *(const float4*)p;
    f4 r; r.v[0] = t.x; r.v[1] = t.y; r.v[2] = t.z; r.v[3] = t.w; return r;
}
__device__ __forceinline__ void st4s(float* p, const float* a) {
    __stcs((float4*)p, make_float4(a[0], a[1], a[2], a[3]));
}

__global__ __launch_bounds__(NT, 1) void gp_main(
    const float* __restrict__ l00r, const float* __restrict__ l00i,
    const float* __restrict__ l01r, const float* __restrict__ l01i,
    const float* __restrict__ l02r, const float* __restrict__ l02i,
    const float* __restrict__ l11r, const float* __restrict__ l11i,
    const float* __restrict__ l12r, const float* __restrict__ l12i,
    const float* __restrict__ l22r, const float* __restrict__ l22i,
    const float* __restrict__ zre,  const float* __restrict__ zim,
    float* __restrict__ out)
{
    __shared__ __align__(16) float sm[214 * JT];
    __shared__ float sRed[42];
    __shared__ float sF[NB];
    __shared__ unsigned int sLast;

    float* sT1r  = sm;              // [16][JT] row t*4+k
    float* sT1i  = sm + 16 * JT;
    float* sIS1r = sm + 32 * JT;    // [4][JT]
    float* sIS1i = sm + 36 * JT;
    float* sAr   = sm + 40 * JT;    // [16][JT]
    float* sAi   = sm + 56 * JT;
    float* sT2r  = sm + 72 * JT;    // [20][JT]
    float* sT2i  = sm + 92 * JT;
    float* sIS2r = sm + 112 * JT;   // [JT]
    float* sIS2i = sm + 113 * JT;
    float* sZr   = sm + 114 * JT;   // [21][JT]
    float* sZi   = sm + 135 * JT;
    float* sM2pr = sm + 156 * JT;   // [4][JT]
    float* sM2pi = sm + 160 * JT;
    float* sDXpr = sm + 164 * JT;   // [4][JT]
    float* sDXpi = sm + 168 * JT;
    float* sDYr  = sm + 172 * JT;   // [4][JT]
    float* sDYi  = sm + 176 * JT;
    float* sDXr  = sm + 180 * JT;   // [JT]
    float* sDXi  = sm + 181 * JT;
    float* sS1pr = sm + 182 * JT;   // [16][JT] per-(t,k) S1 partials
    float* sS1pi = sm + 198 * JT;

    const int flat = threadIdx.x;
    const int jj   = flat & 63;
    const int j    = blockIdx.x * JT + jj;

    // ---- z preload (2 strided iterations) ----
    for (int idx = flat; idx < 21 * JT; idx += NT) {
        int q = idx >> 6, c = idx & 63;
        sZr[idx] = zre[q * NJ + blockIdx.x * JT + c];
        sZi[idx] = zim[q * NJ + blockIdx.x * JT + c];
    }

    // ---- Phase 1a: (t,k,j) fully parallel — all 1024 threads ----
    {
        const int tk = flat >> 6;        // 0..15
        const int t  = tk & 3, k = tk >> 2;
        const int i0 = k * 65536 + t * NJ + j;
        float br = l00r[i0], bi = l00i[i0];
        float nrm = br * br + bi * bi;
        float rn = __fdividef(1.0f, nrm);
        float ar = br * rn, ai = -bi * rn;        // 1/lam00
        float cr = l01r[i0], ci = l01i[i0];
        float bn = cr * cr + ci * ci;
        const int row = (t * 4 + k) * JT + jj;
        sS1pr[row] = bn * ar;
        sS1pi[row] = bn * ai;
        sT1r[row] = cr * ar - ci * ai;
        sT1i[row] = cr * ai + ci * ar;
        sAr[row] = ar;
        sAi[row] = ai;
        float ld = 0.5f * __logf(nrm);
#pragma unroll
        for (int off = 16; off; off >>= 1)
            ld += __shfl_down_sync(0xffffffffu, ld, off);
        if ((flat & 31) == 0) sRed[flat >> 5] = ld;
    }
    __syncthreads();

    // ---- Phase 1b: (t,j) — 256 threads ----
    if (flat < 256) {
        const int t = flat >> 6;
        const int m = t * NJ + j;
        float S1r = l11r[m], S1i = l11i[m];
        float T1re[4], T1im[4];
#pragma unroll
        for (int k = 0; k < 4; ++k) {
            const int row = (t * 4 + k) * JT + jj;
            S1r -= sS1pr[row];
            S1i -= sS1pi[row];
            T1re[k] = sT1r[row];
            T1im[k] = sT1i[row];
        }
        float ns = S1r * S1r + S1i * S1i;
        float rs = __fdividef(1.0f, ns);
        float is1r = S1r * rs, is1i = -S1i * rs;
        sIS1r[t * JT + jj] = is1r;
        sIS1i[t * JT + jj] = is1i;
        float ld = 0.5f * __logf(ns);

        float Br[5], Bi[5];
#pragma unroll
        for (int a = 0; a < 4; ++a) {
            const int ib = (a * 4 + t) * NJ + j;
            Br[a] = l02r[ib]; Bi[a] = l02i[ib];
        }
        { const int ib = t * NJ + j; Br[4] = l12r[ib]; Bi[4] = l12i[ib]; }

        float Gr = -Br[4], Gi = -Bi[4];
#pragma unroll
        for (int a = 0; a < 4; ++a) {
            Gr += Br[a] * T1re[a] + Bi[a] * T1im[a];
            Gi += Bi[a] * T1re[a] - Br[a] * T1im[a];
        }
        // doty_t
        {
            float dyr = 0.f, dyi = 0.f;
#pragma unroll
            for (int i1 = 0; i1 < 4; ++i1) {
                float zr = sZr[(i1 * 4 + t) * JT + jj], zi = sZi[(i1 * 4 + t) * JT + jj];
                dyr += T1re[i1] * zr + T1im[i1] * zi;
                dyi += T1re[i1] * zi - T1im[i1] * zr;
            }
            dyr -= sZr[(16 + t) * JT + jj];
            dyi -= sZi[(16 + t) * JT + jj];
            sDYr[t * JT + jj] = dyr;
            sDYi[t * JT + jj] = dyi;
        }
        // T2 rows + M2/dotx partials
        float M2r = 0.f, M2i = 0.f, dxr = 0.f, dxi = 0.f;
#pragma unroll
        for (int i = 0; i < 5; ++i) {
            float t2r, t2i;
            if (i < 4) {
                float ur = T1re[i] * is1r - T1im[i] * is1i;
                float ui = T1re[i] * is1i + T1im[i] * is1r;
                float are = sAr[(t * 4 + i) * JT + jj];
                float aim = sAi[(t * 4 + i) * JT + jj];
                t2r = ur * Gr - ui * Gi + are * Br[i] - aim * Bi[i];
                t2i = ur * Gi + ui * Gr + are * Bi[i] + aim * Br[i];
            } else {
                float ur = -is1r, ui = is1i;
                float d4 = 2.0f * is1i;
                t2r = ur * Gr - ui * Gi - d4 * Bi[4];
                t2i = ur * Gi + ui * Gr + d4 * Br[4];
            }
            const int row = (i < 4) ? (i * 4 + t) : (16 + t);
            sT2r[row * JT + jj] = t2r;
            sT2i[row * JT + jj] = t2i;
            M2r += Br[i] * t2r + Bi[i] * t2i;
            M2i += Br[i] * t2i - Bi[i] * t2r;
            float zr = sZr[row * JT + jj], zi = sZi[row * JT + jj];
            dxr += t2r * zr + t2i * zi;
            dxi += t2r * zi - t2i * zr;
        }
        sM2pr[t * JT + jj] = M2r;  sM2pi[t * JT + jj] = M2i;
        sDXpr[t * JT + jj] = dxr;  sDXpi[t * JT + jj] = dxi;

#pragma unroll
        for (int off = 16; off; off >>= 1)
            ld += __shfl_down_sync(0xffffffffu, ld, off);
        if ((flat & 31) == 0) sRed[32 + (flat >> 5)] = ld;
    }
    __syncthreads();

    // ---- Phase 1.5: S2, 1/S2, dotx — 64 threads ----
    if (flat < JT) {
        float M2r = sM2pr[flat] + sM2pr[JT + flat] + sM2pr[2 * JT + flat] + sM2pr[3 * JT + flat];
        float M2i = sM2pi[flat] + sM2pi[JT + flat] + sM2pi[2 * JT + flat] + sM2pi[3 * JT + flat];
        float S2r = l22r[j] - M2r, S2i = l22i[j] - M2i;
        float ns2 = S2r * S2r + S2i * S2i;
        float rs2 = __fdividef(1.0f, ns2);
        sIS2r[flat] = S2r * rs2;
        sIS2i[flat] = -S2i * rs2;
        sDXr[flat] = sDXpr[flat] + sDXpr[JT + flat] + sDXpr[2 * JT + flat] + sDXpr[3 * JT + flat]
                   - sZr[20 * JT + flat];
        sDXi[flat] = sDXpi[flat] + sDXpi[JT + flat] + sDXpi[2 * JT + flat] + sDXpi[3 * JT + flat]
                   - sZi[20 * JT + flat];
        float ld = 0.5f * __logf(ns2);
#pragma unroll
        for (int off = 16; off; off >>= 1)
            ld += __shfl_down_sync(0xffffffffu, ld, off);
        if ((flat & 31) == 0) sRed[40 + (flat >> 5)] = ld;
    }
    __syncthreads();

    if (flat == 0) {
        float s = 0.f;
#pragma unroll
        for (int i = 0; i < 42; ++i) s += sRed[i];
        g_partial[blockIdx.x] = s;
        __threadfence();
        unsigned int old = atomicAdd(&g_done, 1u);
        sLast = (old == NB - 1) ? 1u : 0u;
    }

    // ---- Phase 2: 1008 workers = (qg, p, jq); each emits 7 q rows × 4 j ----
    if (flat < 1008) {
        const int qg  = flat / 336;          // 0..2, q-range [7qg, 7qg+7)
        const int rem = flat - qg * 336;
        const int p   = rem >> 4;            // 0..20
        const int jq  = rem & 15;
        const int jj4 = jq * 4;
        const int j0  = blockIdx.x * JT + jj4;
        const int tt  = p & 3, i0 = p >> 2;

        f4 is2r = ld4(&sIS2r[jj4]), is2i = ld4(&sIS2i[jj4]);
        float wr[4], wi[4], ur[4], ui[4], dr[4], di[4];
        if (p < 20) {
            f4 t2r = ld4(&sT2r[p * JT + jj4]), t2i = ld4(&sT2i[p * JT + jj4]);
            f4 s1r = ld4(&sIS1r[tt * JT + jj4]), s1i = ld4(&sIS1i[tt * JT + jj4]);
#pragma unroll
            for (int e = 0; e < 4; ++e) {
                wr[e] = t2r.v[e] * is2r.v[e] - t2i.v[e] * is2i.v[e];
                wi[e] = t2r.v[e] * is2i.v[e] + t2i.v[e] * is2r.v[e];
            }
            if (i0 < 4) {
                f4 t1r = ld4(&sT1r[(tt * 4 + i0) * JT + jj4]);
                f4 t1i = ld4(&sT1i[(tt * 4 + i0) * JT + jj4]);
                f4 ar  = ld4(&sAr [(tt * 4 + i0) * JT + jj4]);
                f4 ai  = ld4(&sAi [(tt * 4 + i0) * JT + jj4]);
#pragma unroll
                for (int e = 0; e < 4; ++e) {
                    ur[e] = t1r.v[e] * s1r.v[e] - t1i.v[e] * s1i.v[e];
                    ui[e] = t1r.v[e] * s1i.v[e] + t1i.v[e] * s1r.v[e];
                    dr[e] = ar.v[e]; di[e] = ai.v[e];
                }
            } else {
#pragma unroll
                for (int e = 0; e < 4; ++e) {
                    ur[e] = -s1r.v[e]; ui[e] = s1i.v[e];
                    dr[e] = 0.f;       di[e] = 2.0f * s1i.v[e];
                }
            }
        } else {
#pragma unroll
            for (int e = 0; e < 4; ++e) {
                wr[e] = -is2r.v[e]; wi[e] = is2i.v[e];
                ur[e] = 0.f; ui[e] = 0.f;
                dr[e] = 0.f; di[e] = 2.0f * is2i.v[e];
            }
        }

        // zout (only qg==0 workers; one per (p, jq))
        if (qg == 0) {
            f4 dxr = ld4(&sDXr[jj4]), dxi = ld4(&sDXi[jj4]);
            f4 dyr = ld4(&sDYr[tt * JT + jj4]), dyi = ld4(&sDYi[tt * JT + jj4]);
            f4 zpr = ld4(&sZr[p * JT + jj4]),  zpi = ld4(&sZi[p * JT + jj4]);
            float za[4], zb[4];
#pragma unroll
            for (int e = 0; e < 4; ++e) {
                za[e] = wr[e] * dxr.v[e] - wi[e] * dxi.v[e]
                      + ur[e] * dyr.v[e] - ui[e] * dyi.v[e]
                      + dr[e] * zpr.v[e] - di[e] * zpi.v[e];
                zb[e] = wr[e] * dxi.v[e] + wi[e] * dxr.v[e]
                      + ur[e] * dyi.v[e] + ui[e] * dyr.v[e]
                      + dr[e] * zpi.v[e] + di[e] * zpr.v[e];
                out[Z_OFF + p * NJ + j0 + e]          = za[e];
                out[Z_OFF + Z_PART + p * NJ + j0 + e] = zb[e];
            }
        }

        const int rowbase = p * 21 * NJ + j0;
        const int q0 = qg * 7;
#pragma unroll
        for (int qq = 0; qq < 7; ++qq) {
            const int q = q0 + qq;
            float cr[4], ci[4];
            if (q < 20) {
                f4 xr = ld4(&sT2r[q * JT + jj4]), xi = ld4(&sT2i[q * JT + jj4]);
#pragma unroll
                for (int e = 0; e < 4; ++e) {
                    cr[e] = wr[e] * xr.v[e] + wi[e] * xi.v[e];
                    ci[e] = wi[e] * xr.v[e] - wr[e] * xi.v[e];
                }
                if (p < 20 && (((p ^ q) & 3) == 0)) {
                    const int i1 = q >> 2;
                    if (i1 < 4) {
                        f4 vr = ld4(&sT1r[(tt * 4 + i1) * JT + jj4]);
                        f4 vi = ld4(&sT1i[(tt * 4 + i1) * JT + jj4]);
#pragma unroll
                        for (int e = 0; e < 4; ++e) {
                            cr[e] += ur[e] * vr.v[e] + ui[e] * vi.v[e];
                            ci[e] += ui[e] * vr.v[e] - ur[e] * vi.v[e];
                        }
                    } else {
#pragma unroll
                        for (int e = 0; e < 4; ++e) { cr[e] -= ur[e]; ci[e] -= ui[e]; }
                    }
                }
            } else {
#pragma unroll
                for (int e = 0; e < 4; ++e) { cr[e] = -wr[e]; ci[e] = -wi[e]; }
            }
            if (p == q) {
#pragma unroll
                for (int e = 0; e < 4; ++e) { cr[e] += dr[e]; ci[e] += di[e]; }
            }
            st4s(&out[rowbase + q * NJ], cr);
            st4s(&out[A_PART + rowbase + q * NJ], ci);
        }
    }

    // ---- fused logdet finalize (last block) ----
    __syncthreads();
    if (sLast) {
        if (flat < NB) sF[flat] = g_partial[flat];
        __syncthreads();
        for (int off = NB / 2; off; off >>= 1) {
            if (flat < off) sF[flat] += sF[flat + off];
            __syncthreads();
        }
        if (flat == 0) {
            out[LD_OFF] = sF[0];
            g_done = 0u;
        }
    }
}

extern "C" void kernel_launch(void* const* d_in, const int* in_sizes, int n_in,
                              void* d_out, int out_size) {
    const float* l00r = (const float*)d_in[0];
    const float* l00i = (const float*)d_in[1];
    const float* l01r = (const float*)d_in[2];
    const float* l01i = (const float*)d_in[3];
    const float* l02r = (const float*)d_in[4];
    const float* l02i = (const float*)d_in[5];
    const float* l11r = (const float*)d_in[6];
    const float* l11i = (const float*)d_in[7];
    const float* l12r = (const float*)d_in[8];
    const float* l12i = (const float*)d_in[9];
    const float* l22r = (const float*)d_in[10];
    const float* l22i = (const float*)d_in[11];
    const float* zre  = (const float*)d_in[12];
    const float* zim  = (const float*)d_in[13];
    float* out = (float*)d_out;

    gp_main<<<NB, NT>>>(l00r, l00i, l01r, l01i, l02r, l02i,
                        l11r, l11i, l12r, l12i, l22r, l22i,
                        zre, zim, out);
}

// round 6
// speedup vs baseline: 1.6250x; 1.0833x over previous
#include <cuda_runtime.h>

#define NJ 16384
#define JT 32
#define NB (NJ / JT)        // 512 blocks
#define NT 512

#define A_PART (21 * 21 * 16384)
#define LD_OFF (2 * A_PART)
#define Z_OFF  (LD_OFF + 1)
#define Z_PART (21 * 16384)

__device__ float g_partial[NB];
__device__ unsigned int g_done;   // zero-init; last block resets each launch

struct f4 { float v[4]; };
__device__ __forceinline__ f4 ld4(const float* p) {
    float4 t = *(const float4*)p;
    f4 r; r.v[0] = t.x; r.v[1] = t.y; r.v[2] = t.z; r.v[3] = t.w; return r;
}
__device__ __forceinline__ void st4s(float* p, const float* a) {
    __stcs((float4*)p, make_float4(a[0], a[1], a[2], a[3]));
}

__global__ __launch_bounds__(NT, 2) void gp_main(
    const float* __restrict__ l00r, const float* __restrict__ l00i,
    const float* __restrict__ l01r, const float* __restrict__ l01i,
    const float* __restrict__ l02r, const float* __restrict__ l02i,
    const float* __restrict__ l11r, const float* __restrict__ l11i,
    const float* __restrict__ l12r, const float* __restrict__ l12i,
    const float* __restrict__ l22r, const float* __restrict__ l22i,
    const float* __restrict__ zre,  const float* __restrict__ zim,
    float* __restrict__ out)
{
    __shared__ __align__(16) float sm[214 * JT];
    __shared__ float sRed[21];
    __shared__ float sF[NB];
    __shared__ unsigned int sLast;

    float* sT1r  = sm;              // [16][JT] row t*4+k
    float* sT1i  = sm + 16 * JT;
    float* sIS1r = sm + 32 * JT;    // [4][JT]
    float* sIS1i = sm + 36 * JT;
    float* sAr   = sm + 40 * JT;    // [16][JT]
    float* sAi   = sm + 56 * JT;
    float* sT2r  = sm + 72 * JT;    // [20][JT]
    float* sT2i  = sm + 92 * JT;
    float* sIS2r = sm + 112 * JT;   // [JT]
    float* sIS2i = sm + 113 * JT;
    float* sZr   = sm + 114 * JT;   // [21][JT]
    float* sZi   = sm + 135 * JT;
    float* sM2pr = sm + 156 * JT;   // [4][JT]
    float* sM2pi = sm + 160 * JT;
    float* sDXpr = sm + 164 * JT;   // [4][JT]
    float* sDXpi = sm + 168 * JT;
    float* sDYr  = sm + 172 * JT;   // [4][JT]
    float* sDYi  = sm + 176 * JT;
    float* sDXr  = sm + 180 * JT;   // [JT]
    float* sDXi  = sm + 181 * JT;
    float* sS1pr = sm + 182 * JT;   // [16][JT] per-(t,k) S1 partials
    float* sS1pi = sm + 198 * JT;

    const int flat = threadIdx.x;
    const int jj   = flat & (JT - 1);
    const int j    = blockIdx.x * JT + jj;

    // ---- z preload ----
    for (int idx = flat; idx < 21 * JT; idx += NT) {
        int q = idx / JT, c = idx - q * JT;
        sZr[idx] = zre[q * NJ + blockIdx.x * JT + c];
        sZi[idx] = zim[q * NJ + blockIdx.x * JT + c];
    }

    // ---- Phase 1a: (t,k,j) fully parallel — all 512 threads ----
    {
        const int tk = flat >> 5;        // 0..15
        const int t  = tk & 3, k = tk >> 2;
        const int i0 = k * 65536 + t * NJ + j;
        float br = l00r[i0], bi = l00i[i0];
        float nrm = br * br + bi * bi;
        float rn = __fdividef(1.0f, nrm);
        float ar = br * rn, ai = -bi * rn;        // 1/lam00
        float cr = l01r[i0], ci = l01i[i0];
        float bn = cr * cr + ci * ci;
        const int row = (t * 4 + k) * JT + jj;
        sS1pr[row] = bn * ar;
        sS1pi[row] = bn * ai;
        sT1r[row] = cr * ar - ci * ai;
        sT1i[row] = cr * ai + ci * ar;
        sAr[row] = ar;
        sAi[row] = ai;
        float ld = 0.5f * __logf(nrm);
#pragma unroll
        for (int off = 16; off; off >>= 1)
            ld += __shfl_down_sync(0xffffffffu, ld, off);
        if ((flat & 31) == 0) sRed[flat >> 5] = ld;
    }
    __syncthreads();

    // ---- Phase 1b: (t,j) — 128 threads ----
    if (flat < 4 * JT) {
        const int t = flat >> 5;         // 0..3
        const int m = t * NJ + j;
        float S1r = l11r[m], S1i = l11i[m];
        float T1re[4], T1im[4];
#pragma unroll
        for (int k = 0; k < 4; ++k) {
            const int row = (t * 4 + k) * JT + jj;
            S1r -= sS1pr[row];
            S1i -= sS1pi[row];
            T1re[k] = sT1r[row];
            T1im[k] = sT1i[row];
        }
        float ns = S1r * S1r + S1i * S1i;
        float rs = __fdividef(1.0f, ns);
        float is1r = S1r * rs, is1i = -S1i * rs;
        sIS1r[t * JT + jj] = is1r;
        sIS1i[t * JT + jj] = is1i;
        float ld = 0.5f * __logf(ns);

        float Br[5], Bi[5];
#pragma unroll
        for (int a = 0; a < 4; ++a) {
            const int ib = (a * 4 + t) * NJ + j;
            Br[a] = l02r[ib]; Bi[a] = l02i[ib];
        }
        { const int ib = t * NJ + j; Br[4] = l12r[ib]; Bi[4] = l12i[ib]; }

        float Gr = -Br[4], Gi = -Bi[4];
#pragma unroll
        for (int a = 0; a < 4; ++a) {
            Gr += Br[a] * T1re[a] + Bi[a] * T1im[a];
            Gi += Bi[a] * T1re[a] - Br[a] * T1im[a];
        }
        // doty_t
        {
            float dyr = 0.f, dyi = 0.f;
#pragma unroll
            for (int i1 = 0; i1 < 4; ++i1) {
                float zr = sZr[(i1 * 4 + t) * JT + jj], zi = sZi[(i1 * 4 + t) * JT + jj];
                dyr += T1re[i1] * zr + T1im[i1] * zi;
                dyi += T1re[i1] * zi - T1im[i1] * zr;
            }
            dyr -= sZr[(16 + t) * JT + jj];
            dyi -= sZi[(16 + t) * JT + jj];
            sDYr[t * JT + jj] = dyr;
            sDYi[t * JT + jj] = dyi;
        }
        // T2 rows + M2/dotx partials
        float M2r = 0.f, M2i = 0.f, dxr = 0.f, dxi = 0.f;
#pragma unroll
        for (int i = 0; i < 5; ++i) {
            float t2r, t2i;
            if (i < 4) {
                float ur = T1re[i] * is1r - T1im[i] * is1i;
                float ui = T1re[i] * is1i + T1im[i] * is1r;
                float are = sAr[(t * 4 + i) * JT + jj];
                float aim = sAi[(t * 4 + i) * JT + jj];
                t2r = ur * Gr - ui * Gi + are * Br[i] - aim * Bi[i];
                t2i = ur * Gi + ui * Gr + are * Bi[i] + aim * Br[i];
            } else {
                float ur = -is1r, ui = is1i;
                float d4 = 2.0f * is1i;
                t2r = ur * Gr - ui * Gi - d4 * Bi[4];
                t2i = ur * Gi + ui * Gr + d4 * Br[4];
            }
            const int row = (i < 4) ? (i * 4 + t) : (16 + t);
            sT2r[row * JT + jj] = t2r;
            sT2i[row * JT + jj] = t2i;
            M2r += Br[i] * t2r + Bi[i] * t2i;
            M2i += Br[i] * t2i - Bi[i] * t2r;
            float zr = sZr[row * JT + jj], zi = sZi[row * JT + jj];
            dxr += t2r * zr + t2i * zi;
            dxi += t2r * zi - t2i * zr;
        }
        sM2pr[t * JT + jj] = M2r;  sM2pi[t * JT + jj] = M2i;
        sDXpr[t * JT + jj] = dxr;  sDXpi[t * JT + jj] = dxi;

#pragma unroll
        for (int off = 16; off; off >>= 1)
            ld += __shfl_down_sync(0xffffffffu, ld, off);
        if ((flat & 31) == 0) sRed[16 + (flat >> 5)] = ld;
    }
    __syncthreads();

    // ---- Phase 1.5: S2, 1/S2, dotx — 32 threads (1 warp) ----
    if (flat < JT) {
        float M2r = sM2pr[flat] + sM2pr[JT + flat] + sM2pr[2 * JT + flat] + sM2pr[3 * JT + flat];
        float M2i = sM2pi[flat] + sM2pi[JT + flat] + sM2pi[2 * JT + flat] + sM2pi[3 * JT + flat];
        float S2r = l22r[j] - M2r, S2i = l22i[j] - M2i;
        float ns2 = S2r * S2r + S2i * S2i;
        float rs2 = __fdividef(1.0f, ns2);
        sIS2r[flat] = S2r * rs2;
        sIS2i[flat] = -S2i * rs2;
        sDXr[flat] = sDXpr[flat] + sDXpr[JT + flat] + sDXpr[2 * JT + flat] + sDXpr[3 * JT + flat]
                   - sZr[20 * JT + flat];
        sDXi[flat] = sDXpi[flat] + sDXpi[JT + flat] + sDXpi[2 * JT + flat] + sDXpi[3 * JT + flat]
                   - sZi[20 * JT + flat];
        float ld = 0.5f * __logf(ns2);
#pragma unroll
        for (int off = 16; off; off >>= 1)
            ld += __shfl_down_sync(0xffffffffu, ld, off);
        if (flat == 0) sRed[20] = ld;
    }
    __syncthreads();

    if (flat == 0) {
        float s = 0.f;
#pragma unroll
        for (int i = 0; i < 21; ++i) s += sRed[i];
        g_partial[blockIdx.x] = s;
        __threadfence();
        unsigned int old = atomicAdd(&g_done, 1u);
        sLast = (old == NB - 1) ? 1u : 0u;
    }

    // ---- Phase 2: 504 workers = (qg, p, jq); each emits 7 q rows × 4 j ----
    if (flat < 504) {
        const int qg  = flat / 168;          // 0..2, q-range [7qg, 7qg+7)
        const int rem = flat - qg * 168;
        const int p   = rem >> 3;            // 0..20
        const int jq  = rem & 7;
        const int jj4 = jq * 4;
        const int j0  = blockIdx.x * JT + jj4;
        const int tt  = p & 3, i0 = p >> 2;

        f4 is2r = ld4(&sIS2r[jj4]), is2i = ld4(&sIS2i[jj4]);
        float wr[4], wi[4], ur[4], ui[4], dr[4], di[4];
        if (p < 20) {
            f4 t2r = ld4(&sT2r[p * JT + jj4]), t2i = ld4(&sT2i[p * JT + jj4]);
            f4 s1r = ld4(&sIS1r[tt * JT + jj4]), s1i = ld4(&sIS1i[tt * JT + jj4]);
#pragma unroll
            for (int e = 0; e < 4; ++e) {
                wr[e] = t2r.v[e] * is2r.v[e] - t2i.v[e] * is2i.v[e];
                wi[e] = t2r.v[e] * is2i.v[e] + t2i.v[e] * is2r.v[e];
            }
            if (i0 < 4) {
                f4 t1r = ld4(&sT1r[(tt * 4 + i0) * JT + jj4]);
                f4 t1i = ld4(&sT1i[(tt * 4 + i0) * JT + jj4]);
                f4 ar  = ld4(&sAr [(tt * 4 + i0) * JT + jj4]);
                f4 ai  = ld4(&sAi [(tt * 4 + i0) * JT + jj4]);
#pragma unroll
                for (int e = 0; e < 4; ++e) {
                    ur[e] = t1r.v[e] * s1r.v[e] - t1i.v[e] * s1i.v[e];
                    ui[e] = t1r.v[e] * s1i.v[e] + t1i.v[e] * s1r.v[e];
                    dr[e] = ar.v[e]; di[e] = ai.v[e];
                }
            } else {
#pragma unroll
                for (int e = 0; e < 4; ++e) {
                    ur[e] = -s1r.v[e]; ui[e] = s1i.v[e];
                    dr[e] = 0.f;       di[e] = 2.0f * s1i.v[e];
                }
            }
        } else {
#pragma unroll
            for (int e = 0; e < 4; ++e) {
                wr[e] = -is2r.v[e]; wi[e] = is2i.v[e];
                ur[e] = 0.f; ui[e] = 0.f;
                dr[e] = 0.f; di[e] = 2.0f * is2i.v[e];
            }
        }

        // zout (only qg==0 workers; one per (p, jq))
        if (qg == 0) {
            f4 dxr = ld4(&sDXr[jj4]), dxi = ld4(&sDXi[jj4]);
            f4 dyr = ld4(&sDYr[tt * JT + jj4]), dyi = ld4(&sDYi[tt * JT + jj4]);
            f4 zpr = ld4(&sZr[p * JT + jj4]),  zpi = ld4(&sZi[p * JT + jj4]);
#pragma unroll
            for (int e = 0; e < 4; ++e) {
                float za = wr[e] * dxr.v[e] - wi[e] * dxi.v[e]
                         + ur[e] * dyr.v[e] - ui[e] * dyi.v[e]
                         + dr[e] * zpr.v[e] - di[e] * zpi.v[e];
                float zb = wr[e] * dxi.v[e] + wi[e] * dxr.v[e]
                         + ur[e] * dyi.v[e] + ui[e] * dyr.v[e]
                         + dr[e] * zpi.v[e] + di[e] * zpr.v[e];
                out[Z_OFF + p * NJ + j0 + e]          = za;
                out[Z_OFF + Z_PART + p * NJ + j0 + e] = zb;
            }
        }

        const int rowbase = p * 21 * NJ + j0;
        const int q0 = qg * 7;
#pragma unroll
        for (int qq = 0; qq < 7; ++qq) {
            const int q = q0 + qq;
            float cr[4], ci[4];
            if (q < 20) {
                f4 xr = ld4(&sT2r[q * JT + jj4]), xi = ld4(&sT2i[q * JT + jj4]);
#pragma unroll
                for (int e = 0; e < 4; ++e) {
                    cr[e] = wr[e] * xr.v[e] + wi[e] * xi.v[e];
                    ci[e] = wi[e] * xr.v[e] - wr[e] * xi.v[e];
                }
                if (p < 20 && (((p ^ q) & 3) == 0)) {
                    const int i1 = q >> 2;
                    if (i1 < 4) {
                        f4 vr = ld4(&sT1r[(tt * 4 + i1) * JT + jj4]);
                        f4 vi = ld4(&sT1i[(tt * 4 + i1) * JT + jj4]);
#pragma unroll
                        for (int e = 0; e < 4; ++e) {
                            cr[e] += ur[e] * vr.v[e] + ui[e] * vi.v[e];
                            ci[e] += ui[e] * vr.v[e] - ur[e] * vi.v[e];
                        }
                    } else {
#pragma unroll
                        for (int e = 0; e < 4; ++e) { cr[e] -= ur[e]; ci[e] -= ui[e]; }
                    }
                }
            } else {
#pragma unroll
                for (int e = 0; e < 4; ++e) { cr[e] = -wr[e]; ci[e] = -wi[e]; }
            }
            if (p == q) {
#pragma unroll
                for (int e = 0; e < 4; ++e) { cr[e] += dr[e]; ci[e] += di[e]; }
            }
            st4s(&out[rowbase + q * NJ], cr);
            st4s(&out[A_PART + rowbase + q * NJ], ci);
        }
    }

    // ---- fused logdet finalize (last block) ----
    __syncthreads();
    if (sLast) {
        if (flat < NB) sF[flat] = g_partial[flat];
        __syncthreads();
        for (int off = NB / 2; off; off >>= 1) {
            if (flat < off) sF[flat] += sF[flat + off];
            __syncthreads();
        }
        if (flat == 0) {
            out[LD_OFF] = sF[0];
            g_done = 0u;
        }
    }
}

extern "C" void kernel_launch(void* const* d_in, const int* in_sizes, int n_in,
                              void* d_out, int out_size) {
    const float* l00r = (const float*)d_in[0];
    const float* l00i = (const float*)d_in[1];
    const float* l01r = (const float*)d_in[2];
    const float* l01i = (const float*)d_in[3];
    const float* l02r = (const float*)d_in[4];
    const float* l02i = (const float*)d_in[5];
    const float* l11r = (const float*)d_in[6];
    const float* l11i = (const float*)d_in[7];
    const float* l12r = (const float*)d_in[8];
    const float* l12i = (const float*)d_in[9];
    const float* l22r = (const float*)d_in[10];
    const float* l22i = (const float*)d_in[11];
    const float* zre  = (const float*)d_in[12];
    const float* zim  = (const float*)d_in[13];
    float* out = (float*)d_out;

    gp_main<<<NB, NT>>>(l00r, l00i, l01r, l01i, l02r, l02i,
                        l11r, l11i, l12r, l12i, l22r, l22i,
                        zre, zim, out);
}

// round 7
// speedup vs baseline: 1.6497x; 1.0152x over previous
#include <cuda_runtime.h>

#define NJ 16384
#define JT 16
#define NB (NJ / JT)        // 1024 blocks
#define NT 256

#define A_PART (21 * 21 * 16384)
#define LD_OFF (2 * A_PART)
#define Z_OFF  (LD_OFF + 1)
#define Z_PART (21 * 16384)

__device__ float g_partial[NB];
__device__ unsigned int g_done;   // zero-init; last block resets each launch

struct f4 { float v[4]; };
__device__ __forceinline__ f4 ld4(const float* p) {
    float4 t = *(const float4*)p;
    f4 r; r.v[0] = t.x; r.v[1] = t.y; r.v[2] = t.z; r.v[3] = t.w; return r;
}
__device__ __forceinline__ void st4s(float* p, const float* a) {
    __stcs((float4*)p, make_float4(a[0], a[1], a[2], a[3]));
}

__global__ __launch_bounds__(NT, 4) void gp_main(
    const float* __restrict__ l00r, const float* __restrict__ l00i,
    const float* __restrict__ l01r, const float* __restrict__ l01i,
    const float* __restrict__ l02r, const float* __restrict__ l02i,
    const float* __restrict__ l11r, const float* __restrict__ l11i,
    const float* __restrict__ l12r, const float* __restrict__ l12i,
    const float* __restrict__ l22r, const float* __restrict__ l22i,
    const float* __restrict__ zre,  const float* __restrict__ zim,
    float* __restrict__ out)
{
    __shared__ __align__(16) float sm[338 * JT];
    __shared__ float sRed[11];
    __shared__ float sF[NT];
    __shared__ unsigned int sLast;

    float* sT1r  = sm;              // [16][JT] row t*4+k
    float* sT1i  = sm + 16 * JT;
    float* sIS1r = sm + 32 * JT;    // [4][JT]
    float* sIS1i = sm + 36 * JT;
    float* sAr   = sm + 40 * JT;    // [16][JT]
    float* sAi   = sm + 56 * JT;
    float* sT2r  = sm + 72 * JT;    // [20][JT]
    float* sT2i  = sm + 92 * JT;
    float* sIS2r = sm + 112 * JT;   // [JT]
    float* sIS2i = sm + 113 * JT;
    float* sZr   = sm + 114 * JT;   // [21][JT]
    float* sZi   = sm + 135 * JT;
    float* sM2pr = sm + 156 * JT;   // [4][JT]
    float* sM2pi = sm + 160 * JT;
    float* sDXpr = sm + 164 * JT;   // [4][JT]
    float* sDXpi = sm + 168 * JT;
    float* sDYr  = sm + 172 * JT;   // [4][JT]
    float* sDYi  = sm + 176 * JT;
    float* sDXr  = sm + 180 * JT;   // [JT]
    float* sDXi  = sm + 181 * JT;
    float* sS1pr = sm + 182 * JT;   // [16][JT]
    float* sS1pi = sm + 198 * JT;
    float* sWr   = sm + 214 * JT;   // [21][JT]
    float* sWi   = sm + 235 * JT;
    float* sUr   = sm + 256 * JT;   // [20][JT]
    float* sUi   = sm + 276 * JT;
    float* sDr   = sm + 296 * JT;   // [21][JT]
    float* sDi   = sm + 317 * JT;

    const int flat = threadIdx.x;
    const int jj   = flat & (JT - 1);
    const int j    = blockIdx.x * JT + jj;

    // ---- z preload ----
    for (int idx = flat; idx < 21 * JT; idx += NT) {
        int q = idx >> 4, c = idx & (JT - 1);
        sZr[idx] = zre[q * NJ + blockIdx.x * JT + c];
        sZi[idx] = zim[q * NJ + blockIdx.x * JT + c];
    }

    // ---- Phase 1a: (t,k,j) — all 256 threads ----
    {
        const int tk = flat >> 4;        // 0..15
        const int t  = tk & 3, k = tk >> 2;
        const int i0 = k * 65536 + t * NJ + j;
        float br = l00r[i0], bi = l00i[i0];
        float nrm = br * br + bi * bi;
        float rn = __fdividef(1.0f, nrm);
        float ar = br * rn, ai = -bi * rn;        // 1/lam00
        float cr = l01r[i0], ci = l01i[i0];
        float bn = cr * cr + ci * ci;
        const int row = (t * 4 + k) * JT + jj;
        sS1pr[row] = bn * ar;
        sS1pi[row] = bn * ai;
        sT1r[row] = cr * ar - ci * ai;
        sT1i[row] = cr * ai + ci * ar;
        sAr[row] = ar;
        sAi[row] = ai;
        float ld = 0.5f * __logf(nrm);
#pragma unroll
        for (int off = 16; off; off >>= 1)
            ld += __shfl_down_sync(0xffffffffu, ld, off);
        if ((flat & 31) == 0) sRed[flat >> 5] = ld;
    }
    __syncthreads();

    // ---- Phase 1b: (t,j) — 64 threads ----
    if (flat < 4 * JT) {
        const int t = flat >> 4;         // 0..3
        const int m = t * NJ + j;
        float S1r = l11r[m], S1i = l11i[m];
        float T1re[4], T1im[4];
#pragma unroll
        for (int k = 0; k < 4; ++k) {
            const int row = (t * 4 + k) * JT + jj;
            S1r -= sS1pr[row];
            S1i -= sS1pi[row];
            T1re[k] = sT1r[row];
            T1im[k] = sT1i[row];
        }
        float ns = S1r * S1r + S1i * S1i;
        float rs = __fdividef(1.0f, ns);
        float is1r = S1r * rs, is1i = -S1i * rs;
        sIS1r[t * JT + jj] = is1r;
        sIS1i[t * JT + jj] = is1i;
        float ld = 0.5f * __logf(ns);

        float Br[5], Bi[5];
#pragma unroll
        for (int a = 0; a < 4; ++a) {
            const int ib = (a * 4 + t) * NJ + j;
            Br[a] = l02r[ib]; Bi[a] = l02i[ib];
        }
        { const int ib = t * NJ + j; Br[4] = l12r[ib]; Bi[4] = l12i[ib]; }

        float Gr = -Br[4], Gi = -Bi[4];
#pragma unroll
        for (int a = 0; a < 4; ++a) {
            Gr += Br[a] * T1re[a] + Bi[a] * T1im[a];
            Gi += Bi[a] * T1re[a] - Br[a] * T1im[a];
        }
        // doty_t
        {
            float dyr = 0.f, dyi = 0.f;
#pragma unroll
            for (int i1 = 0; i1 < 4; ++i1) {
                float zr = sZr[(i1 * 4 + t) * JT + jj], zi = sZi[(i1 * 4 + t) * JT + jj];
                dyr += T1re[i1] * zr + T1im[i1] * zi;
                dyi += T1re[i1] * zi - T1im[i1] * zr;
            }
            dyr -= sZr[(16 + t) * JT + jj];
            dyi -= sZi[(16 + t) * JT + jj];
            sDYr[t * JT + jj] = dyr;
            sDYi[t * JT + jj] = dyi;
        }
        float M2r = 0.f, M2i = 0.f, dxr = 0.f, dxi = 0.f;
#pragma unroll
        for (int i = 0; i < 5; ++i) {
            float t2r, t2i;
            if (i < 4) {
                float ur = T1re[i] * is1r - T1im[i] * is1i;
                float ui = T1re[i] * is1i + T1im[i] * is1r;
                float are = sAr[(t * 4 + i) * JT + jj];
                float aim = sAi[(t * 4 + i) * JT + jj];
                t2r = ur * Gr - ui * Gi + are * Br[i] - aim * Bi[i];
                t2i = ur * Gi + ui * Gr + are * Bi[i] + aim * Br[i];
            } else {
                float ur = -is1r, ui = is1i;
                float d4 = 2.0f * is1i;
                t2r = ur * Gr - ui * Gi - d4 * Bi[4];
                t2i = ur * Gi + ui * Gr + d4 * Br[4];
            }
            const int row = (i < 4) ? (i * 4 + t) : (16 + t);
            sT2r[row * JT + jj] = t2r;
            sT2i[row * JT + jj] = t2i;
            M2r += Br[i] * t2r + Bi[i] * t2i;
            M2i += Br[i] * t2i - Bi[i] * t2r;
            float zr = sZr[row * JT + jj], zi = sZi[row * JT + jj];
            dxr += t2r * zr + t2i * zi;
            dxi += t2r * zi - t2i * zr;
        }
        sM2pr[t * JT + jj] = M2r;  sM2pi[t * JT + jj] = M2i;
        sDXpr[t * JT + jj] = dxr;  sDXpi[t * JT + jj] = dxi;

#pragma unroll
        for (int off = 16; off; off >>= 1)
            ld += __shfl_down_sync(0xffffffffu, ld, off);
        if ((flat & 31) == 0) sRed[8 + (flat >> 5)] = ld;
    }
    __syncthreads();

    // ---- Phase 1.5: S2, 1/S2, dotx — 16 threads ----
    if (flat < JT) {
        float M2r = sM2pr[flat] + sM2pr[JT + flat] + sM2pr[2 * JT + flat] + sM2pr[3 * JT + flat];
        float M2i = sM2pi[flat] + sM2pi[JT + flat] + sM2pi[2 * JT + flat] + sM2pi[3 * JT + flat];
        float S2r = l22r[j] - M2r, S2i = l22i[j] - M2i;
        float ns2 = S2r * S2r + S2i * S2i;
        float rs2 = __fdividef(1.0f, ns2);
        sIS2r[flat] = S2r * rs2;
        sIS2i[flat] = -S2i * rs2;
        sDXr[flat] = sDXpr[flat] + sDXpr[JT + flat] + sDXpr[2 * JT + flat] + sDXpr[3 * JT + flat]
                   - sZr[20 * JT + flat];
        sDXi[flat] = sDXpi[flat] + sDXpi[JT + flat] + sDXpi[2 * JT + flat] + sDXpi[3 * JT + flat]
                   - sZi[20 * JT + flat];
        float ld = 0.5f * __logf(ns2);
#pragma unroll
        for (int off = 8; off; off >>= 1)
            ld += __shfl_down_sync(0x0000ffffu, ld, off);
        if (flat == 0) sRed[10] = ld;
    }
    __syncthreads();

    if (flat == 0) {
        float s = 0.f;
#pragma unroll
        for (int i = 0; i < 11; ++i) s += sRed[i];
        g_partial[blockIdx.x] = s;
        __threadfence();
        unsigned int old = atomicAdd(&g_done, 1u);
        sLast = (old == NB - 1) ? 1u : 0u;
    }

    // ---- Phase 1.75: w, u, d into smem + zout; tasks (p, jj), 336 over 256 ----
    for (int task = flat; task < 21 * JT; task += NT) {
        const int p  = task >> 4;
        const int c  = task & (JT - 1);
        const int tt = p & 3, i0 = p >> 2;
        const float is2r = sIS2r[c], is2i = sIS2i[c];
        float wr, wi, ur = 0.f, ui = 0.f, dr, di;
        if (p < 20) {
            float t2r = sT2r[p * JT + c], t2i = sT2i[p * JT + c];
            wr = t2r * is2r - t2i * is2i;
            wi = t2r * is2i + t2i * is2r;
            float s1r = sIS1r[tt * JT + c], s1i = sIS1i[tt * JT + c];
            if (i0 < 4) {
                float t1r = sT1r[(tt * 4 + i0) * JT + c];
                float t1i = sT1i[(tt * 4 + i0) * JT + c];
                ur = t1r * s1r - t1i * s1i;
                ui = t1r * s1i + t1i * s1r;
                dr = sAr[(tt * 4 + i0) * JT + c];
                di = sAi[(tt * 4 + i0) * JT + c];
            } else {
                ur = -s1r; ui = s1i;
                dr = 0.f;  di = 2.0f * s1i;
            }
            sUr[p * JT + c] = ur;
            sUi[p * JT + c] = ui;
        } else {
            wr = -is2r; wi = is2i;
            dr = 0.f;   di = 2.0f * is2i;
        }
        sWr[p * JT + c] = wr;
        sWi[p * JT + c] = wi;
        sDr[p * JT + c] = dr;
        sDi[p * JT + c] = di;

        // zout_p
        float dxr = sDXr[c], dxi = sDXi[c];
        float dyr = sDYr[tt * JT + c], dyi = sDYi[tt * JT + c];
        float zpr = sZr[p * JT + c], zpi = sZi[p * JT + c];
        float za = wr * dxr - wi * dxi + ur * dyr - ui * dyi + dr * zpr - di * zpi;
        float zb = wr * dxi + wi * dxr + ur * dyi + ui * dyr + dr * zpi + di * zpr;
        const int gj = blockIdx.x * JT + c;
        out[Z_OFF + p * NJ + gj]          = za;
        out[Z_OFF + Z_PART + p * NJ + gj] = zb;
    }
    __syncthreads();

    // ---- Phase 2: 252 workers = (qg, p, jq); 7 q rows × 4 j each ----
    if (flat < 252) {
        const int qg  = flat / 84;           // 0..2
        const int rem = flat - qg * 84;
        const int p   = rem >> 2;            // 0..20
        const int jq  = rem & 3;
        const int jj4 = jq * 4;
        const int j0  = blockIdx.x * JT + jj4;
        const int tt  = p & 3;

        f4 wr = ld4(&sWr[p * JT + jj4]), wi = ld4(&sWi[p * JT + jj4]);
        f4 dr = ld4(&sDr[p * JT + jj4]), di = ld4(&sDi[p * JT + jj4]);
        f4 ur, ui;
        if (p < 20) { ur = ld4(&sUr[p * JT + jj4]); ui = ld4(&sUi[p * JT + jj4]); }

        const int rowbase = p * 21 * NJ + j0;
        const int q0 = qg * 7;
#pragma unroll
        for (int qq = 0; qq < 7; ++qq) {
            const int q = q0 + qq;
            float cr[4], ci[4];
            if (q < 20) {
                f4 xr = ld4(&sT2r[q * JT + jj4]), xi = ld4(&sT2i[q * JT + jj4]);
#pragma unroll
                for (int e = 0; e < 4; ++e) {
                    cr[e] = wr.v[e] * xr.v[e] + wi.v[e] * xi.v[e];
                    ci[e] = wi.v[e] * xr.v[e] - wr.v[e] * xi.v[e];
                }
                if (p < 20 && (((p ^ q) & 3) == 0)) {
                    const int i1 = q >> 2;
                    if (i1 < 4) {
                        f4 vr = ld4(&sT1r[(tt * 4 + i1) * JT + jj4]);
                        f4 vi = ld4(&sT1i[(tt * 4 + i1) * JT + jj4]);
#pragma unroll
                        for (int e = 0; e < 4; ++e) {
                            cr[e] += ur.v[e] * vr.v[e] + ui.v[e] * vi.v[e];
                            ci[e] += ui.v[e] * vr.v[e] - ur.v[e] * vi.v[e];
                        }
                    } else {
#pragma unroll
                        for (int e = 0; e < 4; ++e) { cr[e] -= ur.v[e]; ci[e] -= ui.v[e]; }
                    }
                }
            } else {
#pragma unroll
                for (int e = 0; e < 4; ++e) { cr[e] = -wr.v[e]; ci[e] = -wi.v[e]; }
            }
            if (p == q) {
#pragma unroll
                for (int e = 0; e < 4; ++e) { cr[e] += dr.v[e]; ci[e] += di.v[e]; }
            }
            st4s(&out[rowbase + q * NJ], cr);
            st4s(&out[A_PART + rowbase + q * NJ], ci);
        }
    }

    // ---- fused logdet finalize (last block) ----
    __syncthreads();
    if (sLast) {
        float s = g_partial[flat] + g_partial[flat + 256]
                + g_partial[flat + 512] + g_partial[flat + 768];
        sF[flat] = s;
        __syncthreads();
        for (int off = NT / 2; off; off >>= 1) {
            if (flat < off) sF[flat] += sF[flat + off];
            __syncthreads();
        }
        if (flat == 0) {
            out[LD_OFF] = sF[0];
            g_done = 0u;
        }
    }
}

extern "C" void kernel_launch(void* const* d_in, const int* in_sizes, int n_in,
                              void* d_out, int out_size) {
    const float* l00r = (const float*)d_in[0];
    const float* l00i = (const float*)d_in[1];
    const float* l01r = (const float*)d_in[2];
    const float* l01i = (const float*)d_in[3];
    const float* l02r = (const float*)d_in[4];
    const float* l02i = (const float*)d_in[5];
    const float* l11r = (const float*)d_in[6];
    const float* l11i = (const float*)d_in[7];
    const float* l12r = (const float*)d_in[8];
    const float* l12i = (const float*)d_in[9];
    const float* l22r = (const float*)d_in[10];
    const float* l22i = (const float*)d_in[11];
    const float* zre  = (const float*)d_in[12];
    const float* zim  = (const float*)d_in[13];
    float* out = (float*)d_out;

    gp_main<<<NB, NT>>>(l00r, l00i, l01r, l01i, l02r, l02i,
                        l11r, l11i, l12r, l12i, l22r, l22i,
                        zre, zim, out);
}